// round 3
// baseline (speedup 1.0000x reference)
#include <cuda_runtime.h>
#include <math.h>

typedef unsigned long long ull;

// Problem constants (B=8, C=16, H=W=128, rate=2, stride=1, ksize=3)
#define NB 8
#define NC 16
#define HH 128
#define HD 64          // downsampled H/W
#define PN 4096        // patch positions (64*64)
#define KD 144         // 16*3*3 patch dim
#define VD 256         // 16*4*4 bg patch dim

// GEMM smem geometry
#define SA 130                   // As row stride (floats): conflict-free, 8B-aligned pairs
#define SB 258                   // Bs(dup) row stride (floats)
#define ABUF (16*SA)             // 2080 floats
#define BBUF (16*SB)             // 4128 floats
#define BUFSZ (ABUF + BBUF)      // 6208 floats per pipeline stage
#define SMEM_BYTES (2*BUFSZ*4)   // 49664 bytes (double buffered)

// -------- scratch (device globals; no allocations allowed) --------
__device__ float g_fgp [(size_t)NB * PN * KD];
__device__ float g_kern[(size_t)NB * PN * KD];
__device__ float g_mm  [NB * PN];
__device__ float g_V   [(size_t)NB * PN * VD];
__device__ float g_S   [(size_t)NB * PN * PN];   // scores -> attn in place
__device__ float g_M   [(size_t)NB * PN * VD];

// -------- packed fp32 helpers (Blackwell f32x2) --------
__device__ __forceinline__ void fma2(ull& d, ull a, ull b) {
    asm("fma.rn.f32x2 %0, %1, %2, %0;" : "+l"(d) : "l"(a), "l"(b));
}
__device__ __forceinline__ float2 unpack2(ull v) {
    float2 r;
    asm("mov.b64 {%0, %1}, %2;" : "=f"(r.x), "=f"(r.y) : "l"(v));
    return r;
}

// ============================================================================
// Prep: fgp / normalized kern / mm / V  — one block per (b, l)
// ============================================================================
__global__ void prep_kernel(const float* __restrict__ fg,
                            const float* __restrict__ bg,
                            const float* __restrict__ mask) {
    int l = blockIdx.x, b = blockIdx.y;
    int yl = l >> 6, xl = l & 63;
    int t = threadIdx.x;            // 256 threads

    float kval = 0.f, fval = 0.f;
    if (t < KD) {
        int c = t / 9, rem = t % 9;
        int i = rem / 3, j = rem % 3;
        int y = yl - 1 + i, x = xl - 1 + j;
        if ((unsigned)y < (unsigned)HD && (unsigned)x < (unsigned)HD) {
            size_t base = (size_t)(b * NC + c) * (HH * HH);
            int off = (2 * y) * HH + 2 * x;
            kval = bg[base + off];
            fval = fg[base + off];
        }
    }

    __shared__ float red[8];
    __shared__ float s_invn;
    float s = kval * kval;
    #pragma unroll
    for (int o = 16; o > 0; o >>= 1) s += __shfl_xor_sync(0xffffffffu, s, o);
    if ((t & 31) == 0) red[t >> 5] = s;
    __syncthreads();
    if (t == 0) {
        float tot = 0.f;
        #pragma unroll
        for (int w = 0; w < 8; w++) tot += red[w];
        s_invn = 1.f / fmaxf(sqrtf(tot), 1e-4f);
    }
    __syncthreads();
    float invn = s_invn;

    if (t < KD) {
        size_t o = (size_t)(b * PN + l) * KD + t;
        g_kern[o] = kval * invn;
        g_fgp[o]  = fval;
    }

    {
        int c = t >> 4, rem = t & 15;
        int i = rem >> 2, j = rem & 3;
        int y = 2 * yl - 1 + i, x = 2 * xl - 1 + j;
        float v = 0.f;
        if ((unsigned)y < (unsigned)HH && (unsigned)x < (unsigned)HH)
            v = bg[(size_t)(b * NC + c) * (HH * HH) + y * HH + x];
        g_V[(size_t)(b * PN + l) * VD + t] = v;
    }

    if (t == 0) {
        float ms = 0.f;
        #pragma unroll
        for (int i = 0; i < 3; i++)
            #pragma unroll
            for (int j = 0; j < 3; j++) {
                int y = yl - 1 + i, x = xl - 1 + j;
                if ((unsigned)y < (unsigned)HD && (unsigned)x < (unsigned)HD)
                    ms += mask[(size_t)b * (HH * HH) + (2 * y) * HH + 2 * x];
            }
        g_mm[b * PN + l] = (ms == 0.f) ? 1.f : 0.f;
    }
}

// ============================================================================
// Shared FFMA2 microkernel: 16 k-steps over As[k][128] (k-major) and
// Bs[k][256] (duplicated columns). Each thread: 4 row-pairs x 8 cols.
// ============================================================================
__device__ __forceinline__ void mt_compute(const float* __restrict__ As,
                                           const float* __restrict__ Bs,
                                           int tr, int tc, ull acc[4][8]) {
    #pragma unroll
    for (int k = 0; k < 16; k++) {
        ull a2[4], b2[8];
        const float* ak = As + k * SA + tr * 8;
        const float* bk = Bs + k * SB + tc * 16;
        #pragma unroll
        for (int ip = 0; ip < 4; ip++) a2[ip] = *(const ull*)(ak + 2 * ip);
        #pragma unroll
        for (int j = 0; j < 8; j++)   b2[j]  = *(const ull*)(bk + 2 * j);
        #pragma unroll
        for (int ip = 0; ip < 4; ip++)
            #pragma unroll
            for (int j = 0; j < 8; j++)
                fma2(acc[ip][j], a2[ip], b2[j]);
    }
}

// ============================================================================
// Scores GEMM (NT): S[p,l] = sum_k fgp[p,k] * kern[l,k]
// 128x128 tile, 256 threads, FFMA2, double-buffered smem
// ============================================================================
__global__ void __launch_bounds__(256, 2) score_gemm_kernel() {
    extern __shared__ float smf[];
    int b = blockIdx.z;
    const float* __restrict__ A  = g_fgp  + (size_t)b * PN * KD;
    const float* __restrict__ Bg = g_kern + (size_t)b * PN * KD;
    float* __restrict__ C = g_S + (size_t)b * PN * PN;
    int pm = blockIdx.y * 128, pn = blockIdx.x * 128;

    int tid = threadIdx.x;
    int tr = tid >> 4, tc = tid & 15;
    int rowA = tid >> 2;
    int kk = (tid & 3) * 4;

    ull acc[4][8] = {};
    float4 sa[2], sb[2];

    #pragma unroll
    for (int r = 0; r < 2; r++) {
        int row = rowA + r * 64;
        sa[r] = *(const float4*)(A  + (size_t)(pm + row) * KD + kk);
        sb[r] = *(const float4*)(Bg + (size_t)(pn + row) * KD + kk);
    }

    const int T = KD / 16;   // 9
    for (int t = 0; t < T; t++) {
        float* As = smf + (t & 1) * BUFSZ;
        float* Bs = As + ABUF;
        #pragma unroll
        for (int r = 0; r < 2; r++) {
            int row = rowA + r * 64;
            As[(kk + 0) * SA + row] = sa[r].x;
            As[(kk + 1) * SA + row] = sa[r].y;
            As[(kk + 2) * SA + row] = sa[r].z;
            As[(kk + 3) * SA + row] = sa[r].w;
            *(float2*)(Bs + (kk + 0) * SB + 2 * row) = make_float2(sb[r].x, sb[r].x);
            *(float2*)(Bs + (kk + 1) * SB + 2 * row) = make_float2(sb[r].y, sb[r].y);
            *(float2*)(Bs + (kk + 2) * SB + 2 * row) = make_float2(sb[r].z, sb[r].z);
            *(float2*)(Bs + (kk + 3) * SB + 2 * row) = make_float2(sb[r].w, sb[r].w);
        }
        __syncthreads();
        if (t + 1 < T) {
            int k0 = (t + 1) * 16;
            #pragma unroll
            for (int r = 0; r < 2; r++) {
                int row = rowA + r * 64;
                sa[r] = *(const float4*)(A  + (size_t)(pm + row) * KD + k0 + kk);
                sb[r] = *(const float4*)(Bg + (size_t)(pn + row) * KD + k0 + kk);
            }
        }
        mt_compute(As, Bs, tr, tc, acc);
        __syncthreads();
    }

    #pragma unroll
    for (int ip = 0; ip < 4; ip++) {
        float2 u[8];
        #pragma unroll
        for (int j = 0; j < 8; j++) u[j] = unpack2(acc[ip][j]);
        float* c0 = C + (size_t)(pm + tr * 8 + 2 * ip) * PN + pn + tc * 8;
        float* c1 = c0 + PN;
        *(float4*)(c0)     = make_float4(u[0].x, u[1].x, u[2].x, u[3].x);
        *(float4*)(c0 + 4) = make_float4(u[4].x, u[5].x, u[6].x, u[7].x);
        *(float4*)(c1)     = make_float4(u[0].y, u[1].y, u[2].y, u[3].y);
        *(float4*)(c1 + 4) = make_float4(u[4].y, u[5].y, u[6].y, u[7].y);
    }
}

// ============================================================================
// Softmax over l (row of 4096), in place, float4-vectorized
// ============================================================================
__global__ void __launch_bounds__(256) softmax_kernel() {
    int p = blockIdx.x, b = blockIdx.y;
    float4* __restrict__ row = (float4*)(g_S + ((size_t)b * PN + p) * PN);
    const float4* __restrict__ mm = (const float4*)(g_mm + (size_t)b * PN);
    int t = threadIdx.x;

    float4 zv[4], mv[4];
    float zmax = -1e30f;
    #pragma unroll
    for (int r = 0; r < 4; r++) {
        int l = t + r * 256;
        float4 s = row[l];
        float4 m = mm[l];
        mv[r] = m;
        float4 z = make_float4(10.f * s.x * m.x, 10.f * s.y * m.y,
                               10.f * s.z * m.z, 10.f * s.w * m.w);
        zv[r] = z;
        zmax = fmaxf(zmax, fmaxf(fmaxf(z.x, z.y), fmaxf(z.z, z.w)));
    }

    __shared__ float red[8];
    __shared__ float s_bc;
    #pragma unroll
    for (int o = 16; o > 0; o >>= 1) zmax = fmaxf(zmax, __shfl_xor_sync(0xffffffffu, zmax, o));
    if ((t & 31) == 0) red[t >> 5] = zmax;
    __syncthreads();
    if (t == 0) {
        float m = red[0];
        #pragma unroll
        for (int w = 1; w < 8; w++) m = fmaxf(m, red[w]);
        s_bc = m;
    }
    __syncthreads();
    float m = s_bc;

    float lsum = 0.f;
    #pragma unroll
    for (int r = 0; r < 4; r++) {
        float4 z = zv[r];
        z.x = __expf(z.x - m); z.y = __expf(z.y - m);
        z.z = __expf(z.z - m); z.w = __expf(z.w - m);
        zv[r] = z;
        lsum += z.x + z.y + z.z + z.w;
    }
    #pragma unroll
    for (int o = 16; o > 0; o >>= 1) lsum += __shfl_xor_sync(0xffffffffu, lsum, o);
    __syncthreads();
    if ((t & 31) == 0) red[t >> 5] = lsum;
    __syncthreads();
    if (t == 0) {
        float tot = 0.f;
        #pragma unroll
        for (int w = 0; w < 8; w++) tot += red[w];
        s_bc = 1.f / tot;
    }
    __syncthreads();
    float inv = s_bc;

    #pragma unroll
    for (int r = 0; r < 4; r++) {
        int l = t + r * 256;
        float4 z = zv[r], mmv = mv[r];
        row[l] = make_float4(z.x * inv * mmv.x, z.y * inv * mmv.y,
                             z.z * inv * mmv.z, z.w * inv * mmv.w);
    }
}

// ============================================================================
// Recon GEMM (NN): M[p,r] = sum_l attn[p,l] * V[l,r]   (N=256, K=4096)
// ============================================================================
__global__ void __launch_bounds__(256, 2) recon_gemm_kernel() {
    extern __shared__ float smf[];
    int b = blockIdx.z;
    const float* __restrict__ A  = g_S + (size_t)b * PN * PN;   // attn [P, L]
    const float* __restrict__ Bg = g_V + (size_t)b * PN * VD;   // [L, 256]
    float* __restrict__ C = g_M + (size_t)b * PN * VD;
    int pm = blockIdx.y * 128, pn = blockIdx.x * 128;

    int tid = threadIdx.x;
    int tr = tid >> 4, tc = tid & 15;
    int rowA = tid >> 2;
    int kk = (tid & 3) * 4;
    int kb0 = tid >> 5;          // + r*8
    int nb = (tid & 31) * 4;

    ull acc[4][8] = {};
    float4 sa[2], sb[2];

    #pragma unroll
    for (int r = 0; r < 2; r++) {
        int row = rowA + r * 64;
        sa[r] = *(const float4*)(A + (size_t)(pm + row) * PN + kk);
        int kb = kb0 + r * 8;
        sb[r] = *(const float4*)(Bg + (size_t)kb * VD + pn + nb);
    }

    const int T = PN / 16;   // 256
    for (int t = 0; t < T; t++) {
        float* As = smf + (t & 1) * BUFSZ;
        float* Bs = As + ABUF;
        #pragma unroll
        for (int r = 0; r < 2; r++) {
            int row = rowA + r * 64;
            As[(kk + 0) * SA + row] = sa[r].x;
            As[(kk + 1) * SA + row] = sa[r].y;
            As[(kk + 2) * SA + row] = sa[r].z;
            As[(kk + 3) * SA + row] = sa[r].w;
            int kb = kb0 + r * 8;
            float* bp = Bs + kb * SB + 2 * nb;
            *(float2*)(bp + 0) = make_float2(sb[r].x, sb[r].x);
            *(float2*)(bp + 2) = make_float2(sb[r].y, sb[r].y);
            *(float2*)(bp + 4) = make_float2(sb[r].z, sb[r].z);
            *(float2*)(bp + 6) = make_float2(sb[r].w, sb[r].w);
        }
        __syncthreads();
        if (t + 1 < T) {
            int k0 = (t + 1) * 16;
            #pragma unroll
            for (int r = 0; r < 2; r++) {
                int row = rowA + r * 64;
                sa[r] = *(const float4*)(A + (size_t)(pm + row) * PN + k0 + kk);
                int kb = kb0 + r * 8;
                sb[r] = *(const float4*)(Bg + (size_t)(k0 + kb) * VD + pn + nb);
            }
        }
        mt_compute(As, Bs, tr, tc, acc);
        __syncthreads();
    }

    #pragma unroll
    for (int ip = 0; ip < 4; ip++) {
        float2 u[8];
        #pragma unroll
        for (int j = 0; j < 8; j++) u[j] = unpack2(acc[ip][j]);
        float* c0 = C + (size_t)(pm + tr * 8 + 2 * ip) * VD + pn + tc * 8;
        float* c1 = c0 + VD;
        *(float4*)(c0)     = make_float4(u[0].x, u[1].x, u[2].x, u[3].x);
        *(float4*)(c0 + 4) = make_float4(u[4].x, u[5].x, u[6].x, u[7].x);
        *(float4*)(c1)     = make_float4(u[0].y, u[1].y, u[2].y, u[3].y);
        *(float4*)(c1 + 4) = make_float4(u[4].y, u[5].y, u[6].y, u[7].y);
    }
}

// ============================================================================
// Overlap-add gather
// ============================================================================
__global__ void gather_kernel(float* __restrict__ out) {
    int idx = blockIdx.x * blockDim.x + threadIdx.x;
    if (idx >= NB * NC * HH * HH) return;
    int v = idx & 127;
    int u = (idx >> 7) & 127;
    int c = (idx >> 14) & 15;
    int b = idx >> 18;

    int yh = (u + 1) >> 1;
    int xh = (v + 1) >> 1;
    float acc = 0.f;
    #pragma unroll
    for (int dy = 0; dy < 2; dy++) {
        int y = yh - dy;
        if ((unsigned)y >= (unsigned)HD) continue;
        int i = u + 1 - 2 * y;
        #pragma unroll
        for (int dx = 0; dx < 2; dx++) {
            int x = xh - dx;
            if ((unsigned)x >= (unsigned)HD) continue;
            int j = v + 1 - 2 * x;
            acc += g_M[((size_t)(b * PN + y * 64 + x)) * VD + c * 16 + i * 4 + j];
        }
    }
    out[idx] = 0.25f * acc;
}

// ============================================================================
extern "C" void kernel_launch(void* const* d_in, const int* in_sizes, int n_in,
                              void* d_out, int out_size) {
    const float* fg   = (const float*)d_in[0];
    const float* bg   = (const float*)d_in[1];
    const float* mask = (const float*)d_in[2];
    float* out = (float*)d_out;

    cudaFuncSetAttribute(score_gemm_kernel,
                         cudaFuncAttributeMaxDynamicSharedMemorySize, SMEM_BYTES);
    cudaFuncSetAttribute(recon_gemm_kernel,
                         cudaFuncAttributeMaxDynamicSharedMemorySize, SMEM_BYTES);

    prep_kernel<<<dim3(PN, NB), 256>>>(fg, bg, mask);
    score_gemm_kernel<<<dim3(PN / 128, PN / 128, NB), 256, SMEM_BYTES>>>();
    softmax_kernel<<<dim3(PN, NB), 256>>>();
    recon_gemm_kernel<<<dim3(VD / 128, PN / 128, NB), 256, SMEM_BYTES>>>();
    int total = NB * NC * HH * HH;
    gather_kernel<<<(total + 255) / 256, 256>>>(out);
}

// round 6
// speedup vs baseline: 2.8189x; 2.8189x over previous
#include <cuda_runtime.h>
#include <math.h>

typedef unsigned long long ull;

// Problem constants (B=8, C=16, H=W=128, rate=2, stride=1, ksize=3)
#define NB 8
#define NC 16
#define HH 128
#define HD 64          // downsampled H/W
#define PN 4096        // patch positions (64*64)
#define KD 144         // 16*3*3 patch dim
#define VD 256         // 16*4*4 bg patch dim

// GEMM smem geometry
#define SA 130                   // As row stride (floats)
#define SB 260                   // Bs(dup, natural order) row stride (floats); mult of 4 -> float4 stores aligned
#define ABUF (16*SA)             // 2080 floats (mult of 4)
#define BBUF (16*SB)             // 4160 floats
#define BUFSZ (ABUF + BBUF)      // 6240 floats (mult of 4 -> 16B-aligned stages)
#define SMEM_BYTES (2*BUFSZ*4)   // 49920 bytes (double buffered)

// -------- scratch (device globals; no allocations allowed) --------
__device__ float g_fgp [(size_t)NB * PN * KD];
__device__ float g_kern[(size_t)NB * PN * KD];
__device__ float g_mm  [NB * PN];
__device__ float g_V   [(size_t)NB * PN * VD];
__device__ float g_S   [(size_t)NB * PN * PN];   // scores -> attn in place
__device__ float g_M   [(size_t)NB * PN * VD];

// -------- packed fp32 helpers (Blackwell f32x2) --------
__device__ __forceinline__ void fma2(ull& d, ull a, ull b) {
    asm("fma.rn.f32x2 %0, %1, %2, %0;" : "+l"(d) : "l"(a), "l"(b));
}
__device__ __forceinline__ float2 unpack2(ull v) {
    float2 r;
    asm("mov.b64 {%0, %1}, %2;" : "=f"(r.x), "=f"(r.y) : "l"(v));
    return r;
}

// ============================================================================
// Prep: fgp / normalized kern / mm / V  — one block per (b, l)
// ============================================================================
__global__ void prep_kernel(const float* __restrict__ fg,
                            const float* __restrict__ bg,
                            const float* __restrict__ mask) {
    int l = blockIdx.x, b = blockIdx.y;
    int yl = l >> 6, xl = l & 63;
    int t = threadIdx.x;            // 256 threads

    float kval = 0.f, fval = 0.f;
    if (t < KD) {
        int c = t / 9, rem = t % 9;
        int i = rem / 3, j = rem % 3;
        int y = yl - 1 + i, x = xl - 1 + j;
        if ((unsigned)y < (unsigned)HD && (unsigned)x < (unsigned)HD) {
            size_t base = (size_t)(b * NC + c) * (HH * HH);
            int off = (2 * y) * HH + 2 * x;
            kval = bg[base + off];
            fval = fg[base + off];
        }
    }

    __shared__ float red[8];
    __shared__ float s_invn;
    float s = kval * kval;
    #pragma unroll
    for (int o = 16; o > 0; o >>= 1) s += __shfl_xor_sync(0xffffffffu, s, o);
    if ((t & 31) == 0) red[t >> 5] = s;
    __syncthreads();
    if (t == 0) {
        float tot = 0.f;
        #pragma unroll
        for (int w = 0; w < 8; w++) tot += red[w];
        s_invn = 1.f / fmaxf(sqrtf(tot), 1e-4f);
    }
    __syncthreads();
    float invn = s_invn;

    if (t < KD) {
        size_t o = (size_t)(b * PN + l) * KD + t;
        g_kern[o] = kval * invn;
        g_fgp[o]  = fval;
    }

    {
        int c = t >> 4, rem = t & 15;
        int i = rem >> 2, j = rem & 3;
        int y = 2 * yl - 1 + i, x = 2 * xl - 1 + j;
        float v = 0.f;
        if ((unsigned)y < (unsigned)HH && (unsigned)x < (unsigned)HH)
            v = bg[(size_t)(b * NC + c) * (HH * HH) + y * HH + x];
        g_V[(size_t)(b * PN + l) * VD + t] = v;
    }

    if (t == 0) {
        float ms = 0.f;
        #pragma unroll
        for (int i = 0; i < 3; i++)
            #pragma unroll
            for (int j = 0; j < 3; j++) {
                int y = yl - 1 + i, x = xl - 1 + j;
                if ((unsigned)y < (unsigned)HD && (unsigned)x < (unsigned)HD)
                    ms += mask[(size_t)b * (HH * HH) + (2 * y) * HH + 2 * x];
            }
        g_mm[b * PN + l] = (ms == 0.f) ? 1.f : 0.f;
    }
}

// ============================================================================
// FFMA2 microkernel. As[k][128] k-major (scalar floats). Bs[k] holds 128
// duplicated column pairs in natural order: column c at float offset 2c.
// Thread (tr,tc): rows tr*8..tr*8+7 (4 packed pairs), cols tc+16*j, j=0..7.
// Read b2[j] at Bs + k*SB + 2*tc + 32*j: 16 float2s span all 32 banks -> N=1.
// ============================================================================
__device__ __forceinline__ void mt_compute(const float* __restrict__ As,
                                           const float* __restrict__ Bs,
                                           int tr, int tc, ull acc[4][8]) {
    #pragma unroll
    for (int k = 0; k < 16; k++) {
        ull a2[4], b2[8];
        const float* ak = As + k * SA + tr * 8;
        const float* bk = Bs + k * SB + 2 * tc;
        #pragma unroll
        for (int ip = 0; ip < 4; ip++) a2[ip] = *(const ull*)(ak + 2 * ip);
        #pragma unroll
        for (int j = 0; j < 8; j++)   b2[j]  = *(const ull*)(bk + 32 * j);
        #pragma unroll
        for (int ip = 0; ip < 4; ip++)
            #pragma unroll
            for (int j = 0; j < 8; j++)
                fma2(acc[ip][j], a2[ip], b2[j]);
    }
}

// ============================================================================
// Scores GEMM (NT): S[p,l] = sum_k fgp[p,k] * kern[l,k]
// ============================================================================
__global__ void __launch_bounds__(256, 2) score_gemm_kernel() {
    extern __shared__ float smf[];
    int b = blockIdx.z;
    const float* __restrict__ A  = g_fgp  + (size_t)b * PN * KD;
    const float* __restrict__ Bg = g_kern + (size_t)b * PN * KD;
    float* __restrict__ C = g_S + (size_t)b * PN * PN;
    int pm = blockIdx.y * 128, pn = blockIdx.x * 128;

    int tid = threadIdx.x;
    int tr = tid >> 4, tc = tid & 15;
    int rowA = tid >> 2;             // 0..63 (+64)
    int kk = (tid & 3) * 4;

    ull acc[4][8] = {};
    float4 sa[2], sb[2];

    #pragma unroll
    for (int r = 0; r < 2; r++) {
        int row = rowA + r * 64;
        sa[r] = *(const float4*)(A  + (size_t)(pm + row) * KD + kk);
        sb[r] = *(const float4*)(Bg + (size_t)(pn + row) * KD + kk);
    }

    const int T = KD / 16;   // 9
    for (int t = 0; t < T; t++) {
        float* As = smf + (t & 1) * BUFSZ;
        float* Bs = As + ABUF;
        #pragma unroll
        for (int r = 0; r < 2; r++) {
            int row = rowA + r * 64;
            As[(kk + 0) * SA + row] = sa[r].x;
            As[(kk + 1) * SA + row] = sa[r].y;
            As[(kk + 2) * SA + row] = sa[r].z;
            As[(kk + 3) * SA + row] = sa[r].w;
            // column `row` duplicated at natural position 2*row, per k
            *(float2*)(Bs + (kk + 0) * SB + 2 * row) = make_float2(sb[r].x, sb[r].x);
            *(float2*)(Bs + (kk + 1) * SB + 2 * row) = make_float2(sb[r].y, sb[r].y);
            *(float2*)(Bs + (kk + 2) * SB + 2 * row) = make_float2(sb[r].z, sb[r].z);
            *(float2*)(Bs + (kk + 3) * SB + 2 * row) = make_float2(sb[r].w, sb[r].w);
        }
        __syncthreads();
        if (t + 1 < T) {
            int k0 = (t + 1) * 16;
            #pragma unroll
            for (int r = 0; r < 2; r++) {
                int row = rowA + r * 64;
                sa[r] = *(const float4*)(A  + (size_t)(pm + row) * KD + k0 + kk);
                sb[r] = *(const float4*)(Bg + (size_t)(pn + row) * KD + k0 + kk);
            }
        }
        mt_compute(As, Bs, tr, tc, acc);
        __syncthreads();
    }

    #pragma unroll
    for (int ip = 0; ip < 4; ip++) {
        float2 u[8];
        #pragma unroll
        for (int j = 0; j < 8; j++) u[j] = unpack2(acc[ip][j]);
        float* c0 = C + (size_t)(pm + tr * 8 + 2 * ip) * PN + pn + tc;
        float* c1 = c0 + PN;
        #pragma unroll
        for (int j = 0; j < 8; j++) {
            c0[16 * j] = u[j].x;
            c1[16 * j] = u[j].y;
        }
    }
}

// ============================================================================
// Softmax over l (row of 4096), in place, float4-vectorized
// ============================================================================
__global__ void __launch_bounds__(256) softmax_kernel() {
    int p = blockIdx.x, b = blockIdx.y;
    float4* __restrict__ row = (float4*)(g_S + ((size_t)b * PN + p) * PN);
    const float4* __restrict__ mm = (const float4*)(g_mm + (size_t)b * PN);
    int t = threadIdx.x;

    float4 zv[4], mv[4];
    float zmax = -1e30f;
    #pragma unroll
    for (int r = 0; r < 4; r++) {
        int l = t + r * 256;
        float4 s = row[l];
        float4 m = mm[l];
        mv[r] = m;
        float4 z = make_float4(10.f * s.x * m.x, 10.f * s.y * m.y,
                               10.f * s.z * m.z, 10.f * s.w * m.w);
        zv[r] = z;
        zmax = fmaxf(zmax, fmaxf(fmaxf(z.x, z.y), fmaxf(z.z, z.w)));
    }

    __shared__ float red[8];
    __shared__ float s_bc;
    #pragma unroll
    for (int o = 16; o > 0; o >>= 1) zmax = fmaxf(zmax, __shfl_xor_sync(0xffffffffu, zmax, o));
    if ((t & 31) == 0) red[t >> 5] = zmax;
    __syncthreads();
    if (t == 0) {
        float m = red[0];
        #pragma unroll
        for (int w = 1; w < 8; w++) m = fmaxf(m, red[w]);
        s_bc = m;
    }
    __syncthreads();
    float m = s_bc;

    float lsum = 0.f;
    #pragma unroll
    for (int r = 0; r < 4; r++) {
        float4 z = zv[r];
        z.x = __expf(z.x - m); z.y = __expf(z.y - m);
        z.z = __expf(z.z - m); z.w = __expf(z.w - m);
        zv[r] = z;
        lsum += z.x + z.y + z.z + z.w;
    }
    #pragma unroll
    for (int o = 16; o > 0; o >>= 1) lsum += __shfl_xor_sync(0xffffffffu, lsum, o);
    __syncthreads();
    if ((t & 31) == 0) red[t >> 5] = lsum;
    __syncthreads();
    if (t == 0) {
        float tot = 0.f;
        #pragma unroll
        for (int w = 0; w < 8; w++) tot += red[w];
        s_bc = 1.f / tot;
    }
    __syncthreads();
    float inv = s_bc;

    #pragma unroll
    for (int r = 0; r < 4; r++) {
        int l = t + r * 256;
        float4 z = zv[r], mmv = mv[r];
        row[l] = make_float4(z.x * inv * mmv.x, z.y * inv * mmv.y,
                             z.z * inv * mmv.z, z.w * inv * mmv.w);
    }
}

// ============================================================================
// Recon GEMM (NN): M[p,r] = sum_l attn[p,l] * V[l,r]   (N=256, K=4096)
// ============================================================================
__global__ void __launch_bounds__(256, 2) recon_gemm_kernel() {
    extern __shared__ float smf[];
    int b = blockIdx.z;
    const float* __restrict__ A  = g_S + (size_t)b * PN * PN;   // attn [P, L]
    const float* __restrict__ Bg = g_V + (size_t)b * PN * VD;   // [L, 256]
    float* __restrict__ C = g_M + (size_t)b * PN * VD;
    int pm = blockIdx.y * 128, pn = blockIdx.x * 128;

    int tid = threadIdx.x;
    int tr = tid >> 4, tc = tid & 15;
    int rowA = tid >> 2;
    int kk = (tid & 3) * 4;
    int kb0 = tid >> 5;          // + r*8
    int nb = (tid & 31) * 4;

    ull acc[4][8] = {};
    float4 sa[2], sb[2];

    #pragma unroll
    for (int r = 0; r < 2; r++) {
        int row = rowA + r * 64;
        sa[r] = *(const float4*)(A + (size_t)(pm + row) * PN + kk);
        int kb = kb0 + r * 8;
        sb[r] = *(const float4*)(Bg + (size_t)kb * VD + pn + nb);
    }

    const int T = PN / 16;   // 256
    for (int t = 0; t < T; t++) {
        float* As = smf + (t & 1) * BUFSZ;
        float* Bs = As + ABUF;
        #pragma unroll
        for (int r = 0; r < 2; r++) {
            int row = rowA + r * 64;
            As[(kk + 0) * SA + row] = sa[r].x;
            As[(kk + 1) * SA + row] = sa[r].y;
            As[(kk + 2) * SA + row] = sa[r].z;
            As[(kk + 3) * SA + row] = sa[r].w;
            int kb = kb0 + r * 8;
            // cols nb..nb+3 duplicated at natural positions: 32 contiguous bytes
            float* bp = Bs + kb * SB + 2 * nb;   // SB mult of 4 -> 16B aligned
            *(float4*)(bp + 0) = make_float4(sb[r].x, sb[r].x, sb[r].y, sb[r].y);
            *(float4*)(bp + 4) = make_float4(sb[r].z, sb[r].z, sb[r].w, sb[r].w);
        }
        __syncthreads();
        if (t + 1 < T) {
            int k0 = (t + 1) * 16;
            #pragma unroll
            for (int r = 0; r < 2; r++) {
                int row = rowA + r * 64;
                sa[r] = *(const float4*)(A + (size_t)(pm + row) * PN + k0 + kk);
                int kb = kb0 + r * 8;
                sb[r] = *(const float4*)(Bg + (size_t)(k0 + kb) * VD + pn + nb);
            }
        }
        mt_compute(As, Bs, tr, tc, acc);
        __syncthreads();
    }

    #pragma unroll
    for (int ip = 0; ip < 4; ip++) {
        float2 u[8];
        #pragma unroll
        for (int j = 0; j < 8; j++) u[j] = unpack2(acc[ip][j]);
        float* c0 = C + (size_t)(pm + tr * 8 + 2 * ip) * VD + pn + tc;
        float* c1 = c0 + VD;
        #pragma unroll
        for (int j = 0; j < 8; j++) {
            c0[16 * j] = u[j].x;
            c1[16 * j] = u[j].y;
        }
    }
}

// ============================================================================
// Overlap-add gather
// ============================================================================
__global__ void gather_kernel(float* __restrict__ out) {
    int idx = blockIdx.x * blockDim.x + threadIdx.x;
    if (idx >= NB * NC * HH * HH) return;
    int v = idx & 127;
    int u = (idx >> 7) & 127;
    int c = (idx >> 14) & 15;
    int b = idx >> 18;

    int yh = (u + 1) >> 1;
    int xh = (v + 1) >> 1;
    float acc = 0.f;
    #pragma unroll
    for (int dy = 0; dy < 2; dy++) {
        int y = yh - dy;
        if ((unsigned)y >= (unsigned)HD) continue;
        int i = u + 1 - 2 * y;
        #pragma unroll
        for (int dx = 0; dx < 2; dx++) {
            int x = xh - dx;
            if ((unsigned)x >= (unsigned)HD) continue;
            int j = v + 1 - 2 * x;
            acc += g_M[((size_t)(b * PN + y * 64 + x)) * VD + c * 16 + i * 4 + j];
        }
    }
    out[idx] = 0.25f * acc;
}

// ============================================================================
extern "C" void kernel_launch(void* const* d_in, const int* in_sizes, int n_in,
                              void* d_out, int out_size) {
    const float* fg   = (const float*)d_in[0];
    const float* bg   = (const float*)d_in[1];
    const float* mask = (const float*)d_in[2];
    float* out = (float*)d_out;

    cudaFuncSetAttribute(score_gemm_kernel,
                         cudaFuncAttributeMaxDynamicSharedMemorySize, SMEM_BYTES);
    cudaFuncSetAttribute(recon_gemm_kernel,
                         cudaFuncAttributeMaxDynamicSharedMemorySize, SMEM_BYTES);

    prep_kernel<<<dim3(PN, NB), 256>>>(fg, bg, mask);
    score_gemm_kernel<<<dim3(PN / 128, PN / 128, NB), 256, SMEM_BYTES>>>();
    softmax_kernel<<<dim3(PN, NB), 256>>>();
    recon_gemm_kernel<<<dim3(VD / 128, PN / 128, NB), 256, SMEM_BYTES>>>();
    int total = NB * NC * HH * HH;
    gather_kernel<<<(total + 255) / 256, 256>>>(out);
}

// round 16
// speedup vs baseline: 3.4155x; 1.2117x over previous
#include <cuda_runtime.h>
#include <cuda_bf16.h>
#include <cstdint>
#include <math.h>

// Problem constants (B=8, C=16, H=W=128, rate=2, stride=1, ksize=3)
#define NB 8
#define NC 16
#define HH 128
#define HD 64
#define PN 4096        // patch positions (64*64)
#define KD 144         // 16*3*3 patch dim (9 k-steps of 16)
#define VD 256         // 16*4*4 bg patch dim

// -------- scratch (device globals; no allocations allowed) --------
__device__ __nv_bfloat16 g_fgp_h [(size_t)NB * PN * KD];
__device__ __nv_bfloat16 g_fgp_l [(size_t)NB * PN * KD];
__device__ __nv_bfloat16 g_kern_h[(size_t)NB * PN * KD];
__device__ __nv_bfloat16 g_kern_l[(size_t)NB * PN * KD];
__device__ float         g_mm   [NB * PN];
__device__ __nv_bfloat16 g_vt_h [(size_t)NB * VD * PN];   // V transposed: [b, r, l]
__device__ __nv_bfloat16 g_vt_l [(size_t)NB * VD * PN];
__device__ __nv_bfloat16 g_at_h [(size_t)NB * PN * PN];   // attn hi  [b, p, l]
__device__ __nv_bfloat16 g_at_l [(size_t)NB * PN * PN];   // attn lo
__device__ float         g_S    [(size_t)NB * PN * PN];   // raw scores (fp32)
__device__ float         g_M    [(size_t)NB * PN * VD];

__device__ __forceinline__ void split_bf16(float v, __nv_bfloat16& h, __nv_bfloat16& l) {
    h = __float2bfloat16(v);
    l = __float2bfloat16(v - __bfloat162float(h));
}

// mma.sync m16n8k16 row.col bf16 -> f32 accum (sm_80-class PTX; OK on compute_103)
#define MMA16816(d, a, b)                                                     \
    asm volatile("mma.sync.aligned.m16n8k16.row.col.f32.bf16.bf16.f32 "       \
        "{%0,%1,%2,%3}, {%4,%5,%6,%7}, {%8,%9}, {%0,%1,%2,%3};"               \
        : "+f"((d)[0]), "+f"((d)[1]), "+f"((d)[2]), "+f"((d)[3])              \
        : "r"((a)[0]), "r"((a)[1]), "r"((a)[2]), "r"((a)[3]),                 \
          "r"((b)[0]), "r"((b)[1]))

// ============================================================================
// Prep: bf16 hi/lo fgp & normalized kern, mm, transposed V hi/lo
// ============================================================================
__global__ void prep_kernel(const float* __restrict__ fg,
                            const float* __restrict__ bg,
                            const float* __restrict__ mask) {
    int l = blockIdx.x, b = blockIdx.y;
    int yl = l >> 6, xl = l & 63;
    int t = threadIdx.x;            // 256

    float kval = 0.f, fval = 0.f;
    if (t < KD) {
        int c = t / 9, rem = t % 9;
        int i = rem / 3, j = rem % 3;
        int y = yl - 1 + i, x = xl - 1 + j;
        if ((unsigned)y < (unsigned)HD && (unsigned)x < (unsigned)HD) {
            size_t base = (size_t)(b * NC + c) * (HH * HH);
            int off = (2 * y) * HH + 2 * x;
            kval = bg[base + off];
            fval = fg[base + off];
        }
    }

    __shared__ float red[8];
    __shared__ float s_invn;
    float s = kval * kval;
    #pragma unroll
    for (int o = 16; o > 0; o >>= 1) s += __shfl_xor_sync(0xffffffffu, s, o);
    if ((t & 31) == 0) red[t >> 5] = s;
    __syncthreads();
    if (t == 0) {
        float tot = 0.f;
        #pragma unroll
        for (int w = 0; w < 8; w++) tot += red[w];
        s_invn = 1.f / fmaxf(sqrtf(tot), 1e-4f);
    }
    __syncthreads();
    float invn = s_invn;

    if (t < KD) {
        size_t o = (size_t)(b * PN + l) * KD + t;
        __nv_bfloat16 h, lo;
        split_bf16(kval * invn, h, lo);
        g_kern_h[o] = h; g_kern_l[o] = lo;
        split_bf16(fval, h, lo);
        g_fgp_h[o] = h; g_fgp_l[o] = lo;
    }

    {   // transposed V: Vt[b, r=t, l]
        int c = t >> 4, rem = t & 15;
        int i = rem >> 2, j = rem & 3;
        int y = 2 * yl - 1 + i, x = 2 * xl - 1 + j;
        float v = 0.f;
        if ((unsigned)y < (unsigned)HH && (unsigned)x < (unsigned)HH)
            v = bg[(size_t)(b * NC + c) * (HH * HH) + y * HH + x];
        __nv_bfloat16 h, lo;
        split_bf16(v, h, lo);
        size_t o = (size_t)(b * VD + t) * PN + l;
        g_vt_h[o] = h; g_vt_l[o] = lo;
    }

    if (t == 0) {
        float ms = 0.f;
        #pragma unroll
        for (int i = 0; i < 3; i++)
            #pragma unroll
            for (int j = 0; j < 3; j++) {
                int y = yl - 1 + i, x = xl - 1 + j;
                if ((unsigned)y < (unsigned)HD && (unsigned)x < (unsigned)HD)
                    ms += mask[(size_t)b * (HH * HH) + (2 * y) * HH + 2 * x];
            }
        g_mm[b * PN + l] = (ms == 0.f) ? 1.f : 0.f;
    }
}

// ============================================================================
// Shared bf16-split GEMM core (NT, both operands k-contiguous):
//   C[m,n] = sum_k A[m,k]*B[n,k],  A = Ah+Al, B = Bh+Bl,
//   C += Ah*Bh + Ah*Bl + Al*Bh  (Al*Bl dropped: ~2^-18 relative)
// CTA 128x128, 8 warps (2M x 4N), warp tile 64x32, k-step 16, double buffer.
// Device-side pointers ONLY (device globals bound in __global__ wrappers —
// passing __device__ symbols from host reads the zero host-shadow via ATS).
// ============================================================================
#define SST 24
template <int LDA, int LDB, int LDC, int K>
__device__ __forceinline__ void gemm_core(const __nv_bfloat16* __restrict__ Ah,
                                          const __nv_bfloat16* __restrict__ Al,
                                          const __nv_bfloat16* __restrict__ Bh,
                                          const __nv_bfloat16* __restrict__ Bl,
                                          float* __restrict__ C) {
    __shared__ __nv_bfloat16 smem[2][4][128 * SST];   // 49152 B static

    int pm = blockIdx.y * 128, pn = blockIdx.x * 128;
    int tid = threadIdx.x, lane = tid & 31, w = tid >> 5;
    int wm = (w >> 2) * 64, wn = (w & 3) * 32;
    int qr = lane >> 2, qc = (lane & 3) * 2;

    int lrow = tid >> 1, lko = (tid & 1) * 8;
    const __nv_bfloat16* gAh = Ah + (size_t)(pm + lrow) * LDA + lko;
    const __nv_bfloat16* gAl = Al + (size_t)(pm + lrow) * LDA + lko;
    const __nv_bfloat16* gBh = Bh + (size_t)(pn + lrow) * LDB + lko;
    const __nv_bfloat16* gBl = Bl + (size_t)(pn + lrow) * LDB + lko;

    float acc[4][4][4] = {};
    uint4 pa = *(const uint4*)gAh;
    uint4 pb = *(const uint4*)gAl;
    uint4 pc = *(const uint4*)gBh;
    uint4 pd = *(const uint4*)gBl;

    const int nk = K / 16;
    for (int s = 0; s < nk; s++) {
        __nv_bfloat16 (*st)[128 * SST] = smem[s & 1];
        *(uint4*)&st[0][lrow * SST + lko] = pa;
        *(uint4*)&st[1][lrow * SST + lko] = pb;
        *(uint4*)&st[2][lrow * SST + lko] = pc;
        *(uint4*)&st[3][lrow * SST + lko] = pd;
        __syncthreads();
        if (s + 1 < nk) {
            int k0 = (s + 1) * 16;
            pa = *(const uint4*)(gAh + k0);
            pb = *(const uint4*)(gAl + k0);
            pc = *(const uint4*)(gBh + k0);
            pd = *(const uint4*)(gBl + k0);
        }
        const __nv_bfloat16* sAh = st[0];
        const __nv_bfloat16* sAl = st[1];
        const __nv_bfloat16* sBh = st[2];
        const __nv_bfloat16* sBl = st[3];

        uint32_t afh[4][4], bfh[4][2], bfl[4][2];
        #pragma unroll
        for (int f = 0; f < 4; f++) {
            int r0 = wm + f * 16 + qr;
            afh[f][0] = *(const uint32_t*)&sAh[r0 * SST + qc];
            afh[f][1] = *(const uint32_t*)&sAh[(r0 + 8) * SST + qc];
            afh[f][2] = *(const uint32_t*)&sAh[r0 * SST + qc + 8];
            afh[f][3] = *(const uint32_t*)&sAh[(r0 + 8) * SST + qc + 8];
        }
        #pragma unroll
        for (int g = 0; g < 4; g++) {
            int n0 = wn + g * 8 + qr;
            bfh[g][0] = *(const uint32_t*)&sBh[n0 * SST + qc];
            bfh[g][1] = *(const uint32_t*)&sBh[n0 * SST + qc + 8];
            bfl[g][0] = *(const uint32_t*)&sBl[n0 * SST + qc];
            bfl[g][1] = *(const uint32_t*)&sBl[n0 * SST + qc + 8];
        }
        #pragma unroll
        for (int f = 0; f < 4; f++)
            #pragma unroll
            for (int g = 0; g < 4; g++) {
                MMA16816(acc[f][g], afh[f], bfh[g]);
                MMA16816(acc[f][g], afh[f], bfl[g]);
            }
        #pragma unroll
        for (int f = 0; f < 4; f++) {
            int r0 = wm + f * 16 + qr;
            uint32_t afl[4];
            afl[0] = *(const uint32_t*)&sAl[r0 * SST + qc];
            afl[1] = *(const uint32_t*)&sAl[(r0 + 8) * SST + qc];
            afl[2] = *(const uint32_t*)&sAl[r0 * SST + qc + 8];
            afl[3] = *(const uint32_t*)&sAl[(r0 + 8) * SST + qc + 8];
            #pragma unroll
            for (int g = 0; g < 4; g++)
                MMA16816(acc[f][g], afl, bfh[g]);
        }
        __syncthreads();
    }

    #pragma unroll
    for (int f = 0; f < 4; f++)
        #pragma unroll
        for (int g = 0; g < 4; g++) {
            int row = pm + wm + f * 16 + qr;
            int col = pn + wn + g * 8 + qc;
            *(float2*)&C[(size_t)row * LDC + col] =
                make_float2(acc[f][g][0], acc[f][g][1]);
            *(float2*)&C[(size_t)(row + 8) * LDC + col] =
                make_float2(acc[f][g][2], acc[f][g][3]);
        }
}

// Wrappers binding device globals IN DEVICE CODE (device-side addresses).
__global__ void __launch_bounds__(256) score_gemm_kernel() {
    int b = blockIdx.z;
    gemm_core<KD, KD, PN, KD>(
        g_fgp_h  + (size_t)b * PN * KD,
        g_fgp_l  + (size_t)b * PN * KD,
        g_kern_h + (size_t)b * PN * KD,
        g_kern_l + (size_t)b * PN * KD,
        g_S      + (size_t)b * PN * PN);
}

__global__ void __launch_bounds__(256) recon_gemm_kernel() {
    int b = blockIdx.z;
    gemm_core<PN, PN, VD, PN>(
        g_at_h + (size_t)b * PN * PN,
        g_at_l + (size_t)b * PN * PN,
        g_vt_h + (size_t)b * VD * PN,
        g_vt_l + (size_t)b * VD * PN,
        g_M    + (size_t)b * PN * VD);
}

// ============================================================================
// Softmax over l (4096), reads fp32 scores, writes bf16 hi/lo attn
// ============================================================================
__global__ void __launch_bounds__(256) softmax_kernel() {
    int p = blockIdx.x, b = blockIdx.y;
    const float4* __restrict__ row = (const float4*)(g_S + ((size_t)b * PN + p) * PN);
    const float4* __restrict__ mm = (const float4*)(g_mm + (size_t)b * PN);
    int t = threadIdx.x;

    float4 zv[4], mv[4];
    float zmax = -1e30f;
    #pragma unroll
    for (int r = 0; r < 4; r++) {
        int l = t + r * 256;
        float4 s = row[l];
        float4 m = mm[l];
        mv[r] = m;
        float4 z = make_float4(10.f * s.x * m.x, 10.f * s.y * m.y,
                               10.f * s.z * m.z, 10.f * s.w * m.w);
        zv[r] = z;
        zmax = fmaxf(zmax, fmaxf(fmaxf(z.x, z.y), fmaxf(z.z, z.w)));
    }

    __shared__ float red[8];
    __shared__ float s_bc;
    #pragma unroll
    for (int o = 16; o > 0; o >>= 1) zmax = fmaxf(zmax, __shfl_xor_sync(0xffffffffu, zmax, o));
    if ((t & 31) == 0) red[t >> 5] = zmax;
    __syncthreads();
    if (t == 0) {
        float m = red[0];
        #pragma unroll
        for (int w = 1; w < 8; w++) m = fmaxf(m, red[w]);
        s_bc = m;
    }
    __syncthreads();
    float m = s_bc;

    float lsum = 0.f;
    #pragma unroll
    for (int r = 0; r < 4; r++) {
        float4 z = zv[r];
        z.x = __expf(z.x - m); z.y = __expf(z.y - m);
        z.z = __expf(z.z - m); z.w = __expf(z.w - m);
        zv[r] = z;
        lsum += z.x + z.y + z.z + z.w;
    }
    #pragma unroll
    for (int o = 16; o > 0; o >>= 1) lsum += __shfl_xor_sync(0xffffffffu, lsum, o);
    __syncthreads();
    if ((t & 31) == 0) red[t >> 5] = lsum;
    __syncthreads();
    if (t == 0) {
        float tot = 0.f;
        #pragma unroll
        for (int w = 0; w < 8; w++) tot += red[w];
        s_bc = 1.f / tot;
    }
    __syncthreads();
    float inv = s_bc;

    __nv_bfloat16* ah = g_at_h + ((size_t)b * PN + p) * PN;
    __nv_bfloat16* al = g_at_l + ((size_t)b * PN + p) * PN;
    #pragma unroll
    for (int r = 0; r < 4; r++) {
        int l4 = (t + r * 256) * 4;
        float4 z = zv[r], mmv = mv[r];
        float v0 = z.x * inv * mmv.x, v1 = z.y * inv * mmv.y;
        float v2 = z.z * inv * mmv.z, v3 = z.w * inv * mmv.w;
        __nv_bfloat16 h0, l0, h1, l1, h2, l2, h3, l3;
        split_bf16(v0, h0, l0); split_bf16(v1, h1, l1);
        split_bf16(v2, h2, l2); split_bf16(v3, h3, l3);
        ushort4 ph, pl;
        ph.x = __bfloat16_as_ushort(h0); ph.y = __bfloat16_as_ushort(h1);
        ph.z = __bfloat16_as_ushort(h2); ph.w = __bfloat16_as_ushort(h3);
        pl.x = __bfloat16_as_ushort(l0); pl.y = __bfloat16_as_ushort(l1);
        pl.z = __bfloat16_as_ushort(l2); pl.w = __bfloat16_as_ushort(l3);
        *(ushort4*)(ah + l4) = ph;
        *(ushort4*)(al + l4) = pl;
    }
}

// ============================================================================
// Overlap-add gather
// ============================================================================
__global__ void gather_kernel(float* __restrict__ out) {
    int idx = blockIdx.x * blockDim.x + threadIdx.x;
    if (idx >= NB * NC * HH * HH) return;
    int v = idx & 127;
    int u = (idx >> 7) & 127;
    int c = (idx >> 14) & 15;
    int b = idx >> 18;

    int yh = (u + 1) >> 1;
    int xh = (v + 1) >> 1;
    float acc = 0.f;
    #pragma unroll
    for (int dy = 0; dy < 2; dy++) {
        int y = yh - dy;
        if ((unsigned)y >= (unsigned)HD) continue;
        int i = u + 1 - 2 * y;
        #pragma unroll
        for (int dx = 0; dx < 2; dx++) {
            int x = xh - dx;
            if ((unsigned)x >= (unsigned)HD) continue;
            int j = v + 1 - 2 * x;
            acc += g_M[((size_t)(b * PN + y * 64 + x)) * VD + c * 16 + i * 4 + j];
        }
    }
    out[idx] = 0.25f * acc;
}

// ============================================================================
extern "C" void kernel_launch(void* const* d_in, const int* in_sizes, int n_in,
                              void* d_out, int out_size) {
    const float* fg   = (const float*)d_in[0];
    const float* bg   = (const float*)d_in[1];
    const float* mask = (const float*)d_in[2];
    float* out = (float*)d_out;

    prep_kernel<<<dim3(PN, NB), 256>>>(fg, bg, mask);

    // Scores: S[p,l] = fgp[p,:] . kern[l,:]   (M=N=4096, K=144)
    score_gemm_kernel<<<dim3(PN / 128, PN / 128, NB), 256>>>();

    softmax_kernel<<<dim3(PN, NB), 256>>>();

    // Recon: M[p,r] = attn[p,:] . Vt[r,:]   (M=4096, N=256, K=4096)
    recon_gemm_kernel<<<dim3(VD / 128, PN / 128, NB), 256>>>();

    int total = NB * NC * HH * HH;
    gather_kernel<<<(total + 255) / 256, 256>>>(out);
}